// round 5
// baseline (speedup 1.0000x reference)
#include <cuda_runtime.h>
#include <math.h>

// Problem constants
#define B_  32
#define T_  2048
#define D_  512
#define H_  512
#define G_  2048          // 4*H
#define BT_ 65536         // B*T
#define NCTA_REC 128

// ---------------------------------------------------------------------------
// Scratch (device globals per harness rules: no cudaMalloc anywhere)
// ---------------------------------------------------------------------------
__device__ float g_xg[65536ULL * 2048ULL];   // (T, B, G) layout: xg[t][b][g]
__device__ float g_h[2][B_ * H_];            // double-buffered hidden state
__device__ unsigned g_flags[NCTA_REC];       // monotone per-CTA arrive flags

__device__ __forceinline__ void st_rel_u32(unsigned* p, unsigned v) {
    asm volatile("st.release.gpu.global.u32 [%0], %1;" :: "l"(p), "r"(v));
}
__device__ __forceinline__ uint4 ld_vol_v4(const unsigned* p) {
    uint4 v;
    asm volatile("ld.volatile.global.v4.u32 {%0,%1,%2,%3}, [%4];"
                 : "=r"(v.x), "=r"(v.y), "=r"(v.z), "=r"(v.w) : "l"(p));
    return v;
}

// ---------------------------------------------------------------------------
// Kernel A: xg[t][b][g] = sum_d x[b][t][d] * W[d][g] + bias[g]
// fp32 SIMT GEMM, 128x128 tile, BK=8, 256 threads, 8x8 per-thread tile.
// (exact round-3 version — known correct/fast enough; untouched this round)
// ---------------------------------------------------------------------------
__global__ __launch_bounds__(256) void xg_gemm(const float* __restrict__ x,
                                               const float* __restrict__ W,
                                               const float* __restrict__ bias) {
    __shared__ float As[8][128];   // As[k][m]
    __shared__ float Ws[8][128];   // Ws[k][n]

    const int rowBase = blockIdx.y * 128;   // row in (B*T) space
    const int colBase = blockIdx.x * 128;   // col in G space
    const int tid = threadIdx.x;

    const int arow = tid >> 1;
    const int ak4  = (tid & 1) * 4;
    const int wrow = tid >> 5;
    const int wc4  = (tid & 31) * 4;
    const int tm   = (tid >> 4) * 8;
    const int tn   = (tid & 15) * 8;

    float acc[8][8];
#pragma unroll
    for (int i = 0; i < 8; i++)
#pragma unroll
        for (int j = 0; j < 8; j++) acc[i][j] = 0.f;

    for (int k0 = 0; k0 < 512; k0 += 8) {
        float4 av = *(const float4*)&x[(size_t)(rowBase + arow) * 512 + k0 + ak4];
        As[ak4 + 0][arow] = av.x;
        As[ak4 + 1][arow] = av.y;
        As[ak4 + 2][arow] = av.z;
        As[ak4 + 3][arow] = av.w;
        *(float4*)&Ws[wrow][wc4] =
            *(const float4*)&W[(size_t)(k0 + wrow) * 2048 + colBase + wc4];
        __syncthreads();

#pragma unroll
        for (int kk = 0; kk < 8; kk++) {
            float a[8], w[8];
            *(float4*)&a[0] = *(const float4*)&As[kk][tm];
            *(float4*)&a[4] = *(const float4*)&As[kk][tm + 4];
            *(float4*)&w[0] = *(const float4*)&Ws[kk][tn];
            *(float4*)&w[4] = *(const float4*)&Ws[kk][tn + 4];
#pragma unroll
            for (int i = 0; i < 8; i++)
#pragma unroll
                for (int j = 0; j < 8; j++)
                    acc[i][j] = fmaf(a[i], w[j], acc[i][j]);
        }
        __syncthreads();
    }

    float bb[8];
    *(float4*)&bb[0] = *(const float4*)&bias[colBase + tn];
    *(float4*)&bb[4] = *(const float4*)&bias[colBase + tn + 4];

#pragma unroll
    for (int i = 0; i < 8; i++) {
        int r = rowBase + tm + i;
        int t = r & (T_ - 1);
        int b = r >> 11;
        float* dst = &g_xg[((size_t)t * B_ + b) * G_ + colBase + tn];
        float4 v0 = make_float4(acc[i][0] + bb[0], acc[i][1] + bb[1],
                                acc[i][2] + bb[2], acc[i][3] + bb[3]);
        float4 v1 = make_float4(acc[i][4] + bb[4], acc[i][5] + bb[5],
                                acc[i][6] + bb[6], acc[i][7] + bb[7]);
        *(float4*)&dst[0] = v0;
        *(float4*)&dst[4] = v1;
    }
}

// ---------------------------------------------------------------------------
// Kernel B: persistent recurrence (round-3 compute path, bit-identical).
// NEW: one-hop symmetric barrier — every CTA's warp 0 polls all 128 flags
// (coalesced ld.volatile.v4), then one fence.acq_rel.gpu. No master, no g_go.
// NEW: out stores deferred past the arrive so the release fence only drains
// the tiny g_h store; out stores overlap the poll wait.
// ---------------------------------------------------------------------------
#define WSTRIDE 516
#define SM_WA   0
#define SM_WB   (8 * WSTRIDE)
#define SM_HS   (16 * WSTRIDE)
#define SM_GS   (SM_HS + 32 * WSTRIDE)
#define SM_CS   (SM_GS + 512)
#define SMEM_FLOATS (SM_CS + 128)

__global__ __launch_bounds__(256) void lstm_rec(const float* __restrict__ W,
                                                const float* __restrict__ h0,
                                                const float* __restrict__ c0,
                                                float* __restrict__ out) {
    extern __shared__ float sm[];
    float* Wa = sm + SM_WA;          // Wa[g2][k]
    float* Wb = sm + SM_WB;          // Wb[g2][k]
    float* hs = sm + SM_HS;          // hs[b][k], stride WSTRIDE
    float* gs = sm + SM_GS;          // gs[gl*32 + b]
    float* cs = sm + SM_CS;          // cs[hcl*32 + b]

    const int tid = threadIdx.x;
    const int j   = blockIdx.x;      // 0..127
    const int jb  = j * 4;

    // Load Wh slice into the two planes.
    for (int e = tid; e < 8192; e += 256) {
        int k  = e >> 4;
        int gl = e & 15;
        int gcol = (gl >> 2) * 512 + jb + (gl & 3);
        float v = W[(size_t)(512 + k) * 2048 + gcol];
        float* plane = (gl & 1) ? Wb : Wa;
        plane[(gl >> 1) * WSTRIDE + k] = v;
    }
    if (tid < 128) {
        int b = tid >> 2, hcl = tid & 3;
        cs[hcl * 32 + b] = c0[b * 512 + jb + hcl];
    }
    // Barrier base. All 128 flags are equal at run start (each run advances
    // every flag by exactly T_-1), so one base works for comparing ALL flags.
    __shared__ unsigned s_fb;
    if (tid == 0) s_fb = *(volatile unsigned*)&g_flags[j];
    __syncthreads();
    const unsigned fbase = s_fb;

    const int b     = tid >> 3;            // 0..31
    const int g2    = tid & 7;             // 0..7
    const int gl0   = g2 * 2;
    const int gcol0 = (gl0 >> 2) * 512 + jb + (gl0 & 3);

    const float* wa = &Wa[g2 * WSTRIDE];
    const float* wb = &Wb[g2 * WSTRIDE];

    for (int t = 0; t < T_; t++) {
        // Prefetch xg for this thread (independent of h)
        float2 xg2 = *(const float2*)&g_xg[((size_t)t * B_ + b) * G_ + gcol0];

        // Broadcast current h into SMEM
        const float* hsrc = (t == 0) ? h0 : g_h[t & 1];
        for (int i4 = tid; i4 < 4096; i4 += 256) {
            int bb = i4 >> 7, k4 = (i4 & 127) * 4;
            *(float4*)&hs[bb * WSTRIDE + k4] = *(const float4*)&hsrc[bb * 512 + k4];
        }
        __syncthreads();

        // Two K=512 dot products per thread: 3x LDS.128 + 8 FFMA per 4 k.
        float acc0 = xg2.x, acc1 = xg2.y;
        const float* hrow = &hs[b * WSTRIDE];
#pragma unroll 4
        for (int k = 0; k < 512; k += 4) {
            float4 h4 = *(const float4*)&hrow[k];
            float4 a4 = *(const float4*)&wa[k];
            float4 b4 = *(const float4*)&wb[k];
            acc0 = fmaf(h4.x, a4.x, acc0); acc1 = fmaf(h4.x, b4.x, acc1);
            acc0 = fmaf(h4.y, a4.y, acc0); acc1 = fmaf(h4.y, b4.y, acc1);
            acc0 = fmaf(h4.z, a4.z, acc0); acc1 = fmaf(h4.z, b4.z, acc1);
            acc0 = fmaf(h4.w, a4.w, acc0); acc1 = fmaf(h4.w, b4.w, acc1);
        }
        gs[gl0 * 32 + b]       = acc0;
        gs[(gl0 + 1) * 32 + b] = acc1;
        __syncthreads();

        // Gate combine: 128 threads, one (b, hcl) each. h,c kept in registers;
        // only the critical g_h store happens before the arrive.
        float h_r = 0.f, c_r = 0.f;
        int bb = tid >> 2, hcl = tid & 3;
        if (tid < 128) {
            float iv = gs[(0  + hcl) * 32 + bb];
            float fv = gs[(4  + hcl) * 32 + bb];
            float gv = gs[(8  + hcl) * 32 + bb];
            float ov = gs[(12 + hcl) * 32 + bb];
            iv = 1.f / (1.f + expf(-iv));
            fv = 1.f / (1.f + expf(-fv));
            gv = tanhf(gv);
            ov = 1.f / (1.f + expf(-ov));
            c_r = fv * cs[hcl * 32 + bb] + iv * gv;
            cs[hcl * 32 + bb] = c_r;
            h_r = ov * tanhf(c_r);
            g_h[(t + 1) & 1][bb * 512 + jb + hcl] = h_r;     // critical path only
        }
        __syncthreads();   // g_h stores done before the arrive below

        if (t < T_ - 1) {
            const unsigned tgt = fbase + (unsigned)t + 1u;
            if (tid == 0) st_rel_u32(&g_flags[j], tgt);      // arrive (tiny drain)

            // Deferred out store — overlaps the barrier wait below.
            if (tid < 128)
                out[((size_t)bb * T_ + t) * H_ + jb + hcl] = h_r;

            // One-hop wait: warp 0 polls all 128 flags, coalesced v4 loads.
            if (tid < 32) {
                const unsigned* fp = g_flags + tid * 4;
                bool ok;
                do {
                    uint4 v = ld_vol_v4(fp);
                    ok = ((int)(v.x - tgt) >= 0) & ((int)(v.y - tgt) >= 0) &
                         ((int)(v.z - tgt) >= 0) & ((int)(v.w - tgt) >= 0);
                } while (!__all_sync(0xffffffffu, ok));
                asm volatile("fence.acq_rel.gpu;" ::: "memory");
            }
            __syncthreads();
        } else {
            // Last step: no barrier; store everything.
            if (tid < 128) {
                out[((size_t)bb * T_ + t) * H_ + jb + hcl]            = h_r;
                out[(size_t)BT_ * H_ + bb * 512 + jb + hcl]           = h_r;  // h_T
                out[(size_t)BT_ * H_ + B_ * H_ + bb * 512 + jb + hcl] = c_r;  // c_T
            }
        }
    }
}

// ---------------------------------------------------------------------------
// Launcher
// ---------------------------------------------------------------------------
extern "C" void kernel_launch(void* const* d_in, const int* in_sizes, int n_in,
                              void* d_out, int out_size) {
    const float* x    = (const float*)d_in[0];   // (B, T, D)
    const float* W    = (const float*)d_in[1];   // (D+H, 4H)
    const float* bias = (const float*)d_in[2];   // (4H,)
    const float* h0   = (const float*)d_in[3];   // (B, H)
    const float* c0   = (const float*)d_in[4];   // (B, H)
    float* out = (float*)d_out;                  // outputs | h_T | c_T

    dim3 grid(G_ / 128, BT_ / 128);
    xg_gemm<<<grid, 256>>>(x, W, bias);

    size_t smem = SMEM_FLOATS * sizeof(float);
    cudaFuncSetAttribute(lstm_rec, cudaFuncAttributeMaxDynamicSharedMemorySize,
                         (int)smem);
    lstm_rec<<<NCTA_REC, 256, smem>>>(W, h0, c0, out);
}

// round 6
// speedup vs baseline: 1.2706x; 1.2706x over previous
#include <cuda_runtime.h>
#include <math.h>

// Problem constants
#define B_  32
#define T_  2048
#define D_  512
#define H_  512
#define G_  2048          // 4*H
#define BT_ 65536         // B*T
#define NCTA_REC 128

// ---------------------------------------------------------------------------
// Scratch (device globals per harness rules: no cudaMalloc anywhere)
// ---------------------------------------------------------------------------
__device__ float g_xg[65536ULL * 2048ULL];   // (T, B, G) layout: xg[t][b][g]
__device__ float g_h[2][B_ * H_];            // double-buffered hidden state
__device__ unsigned g_flags[NCTA_REC];       // monotone per-CTA arrive flags
__device__ unsigned g_go;                    // monotone master release flag

__device__ __forceinline__ unsigned ld_acq_u32(const unsigned* p) {
    unsigned v;
    asm volatile("ld.acquire.gpu.global.u32 %0, [%1];" : "=r"(v) : "l"(p));
    return v;
}
__device__ __forceinline__ void st_rel_u32(unsigned* p, unsigned v) {
    asm volatile("st.release.gpu.global.u32 [%0], %1;" :: "l"(p), "r"(v));
}

// ---------------------------------------------------------------------------
// Kernel A: xg[t][b][g] = sum_d x[b][t][d] * W[d][g] + bias[g]
// fp32 SIMT GEMM, 128x128 tile, BK=8, 256 threads, 8x8 per-thread tile.
// (round-3 version, untouched)
// ---------------------------------------------------------------------------
__global__ __launch_bounds__(256) void xg_gemm(const float* __restrict__ x,
                                               const float* __restrict__ W,
                                               const float* __restrict__ bias) {
    __shared__ float As[8][128];   // As[k][m]
    __shared__ float Ws[8][128];   // Ws[k][n]

    const int rowBase = blockIdx.y * 128;
    const int colBase = blockIdx.x * 128;
    const int tid = threadIdx.x;

    const int arow = tid >> 1;
    const int ak4  = (tid & 1) * 4;
    const int wrow = tid >> 5;
    const int wc4  = (tid & 31) * 4;
    const int tm   = (tid >> 4) * 8;
    const int tn   = (tid & 15) * 8;

    float acc[8][8];
#pragma unroll
    for (int i = 0; i < 8; i++)
#pragma unroll
        for (int j = 0; j < 8; j++) acc[i][j] = 0.f;

    for (int k0 = 0; k0 < 512; k0 += 8) {
        float4 av = *(const float4*)&x[(size_t)(rowBase + arow) * 512 + k0 + ak4];
        As[ak4 + 0][arow] = av.x;
        As[ak4 + 1][arow] = av.y;
        As[ak4 + 2][arow] = av.z;
        As[ak4 + 3][arow] = av.w;
        *(float4*)&Ws[wrow][wc4] =
            *(const float4*)&W[(size_t)(k0 + wrow) * 2048 + colBase + wc4];
        __syncthreads();

#pragma unroll
        for (int kk = 0; kk < 8; kk++) {
            float a[8], w[8];
            *(float4*)&a[0] = *(const float4*)&As[kk][tm];
            *(float4*)&a[4] = *(const float4*)&As[kk][tm + 4];
            *(float4*)&w[0] = *(const float4*)&Ws[kk][tn];
            *(float4*)&w[4] = *(const float4*)&Ws[kk][tn + 4];
#pragma unroll
            for (int i = 0; i < 8; i++)
#pragma unroll
                for (int j = 0; j < 8; j++)
                    acc[i][j] = fmaf(a[i], w[j], acc[i][j]);
        }
        __syncthreads();
    }

    float bb[8];
    *(float4*)&bb[0] = *(const float4*)&bias[colBase + tn];
    *(float4*)&bb[4] = *(const float4*)&bias[colBase + tn + 4];

#pragma unroll
    for (int i = 0; i < 8; i++) {
        int r = rowBase + tm + i;
        int t = r & (T_ - 1);
        int b = r >> 11;
        float* dst = &g_xg[((size_t)t * B_ + b) * G_ + colBase + tn];
        float4 v0 = make_float4(acc[i][0] + bb[0], acc[i][1] + bb[1],
                                acc[i][2] + bb[2], acc[i][3] + bb[3]);
        float4 v1 = make_float4(acc[i][4] + bb[4], acc[i][5] + bb[5],
                                acc[i][6] + bb[6], acc[i][7] + bb[7]);
        *(float4*)&dst[0] = v0;
        *(float4*)&dst[4] = v1;
    }
}

// ---------------------------------------------------------------------------
// Kernel B: persistent recurrence. CTA j owns h-columns [4j, 4j+4) -> 16 gate
// columns (gl = gtype*4 + hcl). Wh slice in two SMEM planes + c-state resident
// across all 2048 steps. Barrier = round-3 master-aggregator (best measured).
//
// NEW dot-phase mapping (SMEM-crossbar rebalance):
//   thread = (bp, gp, ks):  bp=tid>>4 (16 batch-pairs), gp=(tid>>1)&7
//   (8 gate-col pairs, same pairing as before), ks=tid&1 (k half).
//   Each thread: 2 batches x 2 gate cols over K=256 -> per 4k:
//   4x LDS.128 for 16 FMA (was 3x LDS.128 per 8 FMA).
//   k-half partials combined via gs2[2][16][32] in the gate-combine phase.
// ---------------------------------------------------------------------------
#define WSTRIDE 516
#define SM_WA   0
#define SM_WB   (8 * WSTRIDE)            // 4128
#define SM_HS   (16 * WSTRIDE)           // 8256
#define SM_GS2  (SM_HS + 32 * WSTRIDE)   // 24768
#define SM_CS   (SM_GS2 + 1024)          // 25792
#define SMEM_FLOATS (SM_CS + 128)        // 25920 floats = 103.7 KB

__global__ __launch_bounds__(256) void lstm_rec(const float* __restrict__ W,
                                                const float* __restrict__ h0,
                                                const float* __restrict__ c0,
                                                float* __restrict__ out) {
    extern __shared__ float sm[];
    float* Wa  = sm + SM_WA;         // Wa[gp][k]  (even gl of pair)
    float* Wb  = sm + SM_WB;         // Wb[gp][k]  (odd gl of pair)
    float* hs  = sm + SM_HS;         // hs[b][k], stride WSTRIDE
    float* gs2 = sm + SM_GS2;        // gs2[ks*512 + gl*32 + b]
    float* cs  = sm + SM_CS;         // cs[hcl*32 + b]

    const int tid = threadIdx.x;
    const int j   = blockIdx.x;      // 0..127
    const int jb  = j * 4;

    // Load Wh slice into the two planes (same layout as round 3).
    for (int e = tid; e < 8192; e += 256) {
        int k  = e >> 4;
        int gl = e & 15;
        int gcol = (gl >> 2) * 512 + jb + (gl & 3);
        float v = W[(size_t)(512 + k) * 2048 + gcol];
        float* plane = (gl & 1) ? Wb : Wa;
        plane[(gl >> 1) * WSTRIDE + k] = v;
    }
    if (tid < 128) {
        int b = tid >> 2, hcl = tid & 3;
        cs[hcl * 32 + b] = c0[b * 512 + jb + hcl];
    }
    // Barrier bases (uniform at run start; monotone across graph replays).
    __shared__ unsigned s_fb, s_gb;
    if (tid == 0) {
        s_fb = *(volatile unsigned*)&g_flags[j];
        s_gb = *(volatile unsigned*)&g_go;
    }
    __syncthreads();
    const unsigned fbase = s_fb;
    const unsigned gbase = s_gb;

    // Dot-phase thread mapping
    const int bp = tid >> 4;               // 0..15
    const int gp = (tid >> 1) & 7;         // 0..7
    const int ks = tid & 1;                // 0..1
    const int b0 = 2 * bp;
    const int b1 = b0 + 1;
    const int gl0 = 2 * gp;                // even; gl0,gl0+1 share gate type
    const int gcol0 = (gl0 >> 2) * 512 + jb + (gl0 & 3);
    const int kbase = ks * 256;

    const float* wa = &Wa[gp * WSTRIDE];
    const float* wb = &Wb[gp * WSTRIDE];
    const float* hrow0 = &hs[b0 * WSTRIDE];
    const float* hrow1 = &hs[b1 * WSTRIDE];

    for (int t = 0; t < T_; t++) {
        // xg prefetch: only the ks==0 half seeds with xg (ks==1 seeds 0).
        float2 xg_b0 = make_float2(0.f, 0.f), xg_b1 = make_float2(0.f, 0.f);
        if (ks == 0) {
            xg_b0 = *(const float2*)&g_xg[((size_t)t * B_ + b0) * G_ + gcol0];
            xg_b1 = *(const float2*)&g_xg[((size_t)t * B_ + b1) * G_ + gcol0];
        }

        // Broadcast current h into SMEM
        const float* hsrc = (t == 0) ? h0 : g_h[t & 1];
        for (int i4 = tid; i4 < 4096; i4 += 256) {
            int bb = i4 >> 7, k4 = (i4 & 127) * 4;
            *(float4*)&hs[bb * WSTRIDE + k4] = *(const float4*)&hsrc[bb * 512 + k4];
        }
        __syncthreads();

        // 2 batches x 2 gate cols x K=256: 4x LDS.128 + 16 FMA per 4k.
        float a00 = xg_b0.x, a01 = xg_b0.y;   // (b0,gl0) (b0,gl1)
        float a10 = xg_b1.x, a11 = xg_b1.y;   // (b1,gl0) (b1,gl1)
#pragma unroll 4
        for (int k = kbase; k < kbase + 256; k += 4) {
            float4 h0v = *(const float4*)&hrow0[k];
            float4 h1v = *(const float4*)&hrow1[k];
            float4 a4  = *(const float4*)&wa[k];
            float4 b4  = *(const float4*)&wb[k];
            a00 = fmaf(h0v.x, a4.x, a00); a01 = fmaf(h0v.x, b4.x, a01);
            a10 = fmaf(h1v.x, a4.x, a10); a11 = fmaf(h1v.x, b4.x, a11);
            a00 = fmaf(h0v.y, a4.y, a00); a01 = fmaf(h0v.y, b4.y, a01);
            a10 = fmaf(h1v.y, a4.y, a10); a11 = fmaf(h1v.y, b4.y, a11);
            a00 = fmaf(h0v.z, a4.z, a00); a01 = fmaf(h0v.z, b4.z, a01);
            a10 = fmaf(h1v.z, a4.z, a10); a11 = fmaf(h1v.z, b4.z, a11);
            a00 = fmaf(h0v.w, a4.w, a00); a01 = fmaf(h0v.w, b4.w, a01);
            a10 = fmaf(h1v.w, a4.w, a10); a11 = fmaf(h1v.w, b4.w, a11);
        }
        float* g0 = &gs2[ks * 512];
        g0[gl0 * 32 + b0]       = a00;
        g0[(gl0 + 1) * 32 + b0] = a01;
        g0[gl0 * 32 + b1]       = a10;
        g0[(gl0 + 1) * 32 + b1] = a11;
        __syncthreads();

        // Gate combine: 128 threads, one (b, hcl) each; sum the two k-halves.
        if (tid < 128) {
            int bb = tid >> 2, hcl = tid & 3;
            float iv = gs2[(0  + hcl) * 32 + bb] + gs2[512 + (0  + hcl) * 32 + bb];
            float fv = gs2[(4  + hcl) * 32 + bb] + gs2[512 + (4  + hcl) * 32 + bb];
            float gv = gs2[(8  + hcl) * 32 + bb] + gs2[512 + (8  + hcl) * 32 + bb];
            float ov = gs2[(12 + hcl) * 32 + bb] + gs2[512 + (12 + hcl) * 32 + bb];
            iv = 1.f / (1.f + expf(-iv));
            fv = 1.f / (1.f + expf(-fv));
            gv = tanhf(gv);
            ov = 1.f / (1.f + expf(-ov));
            float c = fv * cs[hcl * 32 + bb] + iv * gv;
            cs[hcl * 32 + bb] = c;
            float h = ov * tanhf(c);
            g_h[(t + 1) & 1][bb * 512 + jb + hcl] = h;       // critical path
            out[((size_t)bb * T_ + t) * H_ + jb + hcl] = h;  // outputs[b][t][hc]
            if (t == T_ - 1) {
                out[(size_t)BT_ * H_ + bb * 512 + jb + hcl]           = h;  // h_T
                out[(size_t)BT_ * H_ + B_ * H_ + bb * 512 + jb + hcl] = c;  // c_T
            }
        }
        __syncthreads();   // all g_h stores done before the arrive below

        // Round-3 master-aggregated barrier (best measured variant).
        if (t < T_ - 1) {
            const unsigned step = (unsigned)t + 1u;
            if (tid == 0) st_rel_u32(&g_flags[j], fbase + step);  // arrive
            if (j == 0) {
                if (tid < NCTA_REC) {
                    while ((int)(ld_acq_u32(&g_flags[tid]) - (fbase + step)) < 0) { }
                }
                __syncthreads();
                if (tid == 0) st_rel_u32(&g_go, gbase + step);
            } else {
                if (tid == 0) {
                    while ((int)(ld_acq_u32(&g_go) - (gbase + step)) < 0) { }
                }
                __syncthreads();
            }
        }
    }
}

// ---------------------------------------------------------------------------
// Launcher
// ---------------------------------------------------------------------------
extern "C" void kernel_launch(void* const* d_in, const int* in_sizes, int n_in,
                              void* d_out, int out_size) {
    const float* x    = (const float*)d_in[0];   // (B, T, D)
    const float* W    = (const float*)d_in[1];   // (D+H, 4H)
    const float* bias = (const float*)d_in[2];   // (4H,)
    const float* h0   = (const float*)d_in[3];   // (B, H)
    const float* c0   = (const float*)d_in[4];   // (B, H)
    float* out = (float*)d_out;                  // outputs | h_T | c_T

    dim3 grid(G_ / 128, BT_ / 128);
    xg_gemm<<<grid, 256>>>(x, W, bias);

    size_t smem = SMEM_FLOATS * sizeof(float);
    cudaFuncSetAttribute(lstm_rec, cudaFuncAttributeMaxDynamicSharedMemorySize,
                         (int)smem);
    lstm_rec<<<NCTA_REC, 256, smem>>>(W, h0, c0, out);
}

// round 7
// speedup vs baseline: 1.3409x; 1.0553x over previous
#include <cuda_runtime.h>
#include <math.h>

// Problem constants
#define B_  32
#define T_  2048
#define D_  512
#define H_  512
#define G_  2048          // 4*H
#define BT_ 65536         // B*T
#define NCTA_REC 128

// ---------------------------------------------------------------------------
// Scratch (device globals per harness rules: no cudaMalloc anywhere)
// ---------------------------------------------------------------------------
__device__ float g_xg[65536ULL * 2048ULL];   // (T, B, G) layout: xg[t][b][g]
__device__ float g_h[2][B_ * H_];            // double-buffered hidden state
__device__ unsigned g_flags[NCTA_REC];       // monotone per-CTA arrive flags
__device__ unsigned g_go;                    // monotone master release flag

__device__ __forceinline__ unsigned ld_vol_u32(const unsigned* p) {
    unsigned v;
    asm volatile("ld.volatile.global.u32 %0, [%1];" : "=r"(v) : "l"(p));
    return v;
}
__device__ __forceinline__ void st_rel_u32(unsigned* p, unsigned v) {
    asm volatile("st.release.gpu.global.u32 [%0], %1;" :: "l"(p), "r"(v));
}
__device__ __forceinline__ void fence_acq_rel_gpu() {
    asm volatile("fence.acq_rel.gpu;" ::: "memory");
}

// ---------------------------------------------------------------------------
// Kernel A: xg[t][b][g] = sum_d x[b][t][d] * W[d][g] + bias[g]
// fp32 SIMT GEMM, 128x128 tile, BK=8, 256 threads, 8x8 per-thread tile.
// (round-3 version, untouched)
// ---------------------------------------------------------------------------
__global__ __launch_bounds__(256) void xg_gemm(const float* __restrict__ x,
                                               const float* __restrict__ W,
                                               const float* __restrict__ bias) {
    __shared__ float As[8][128];   // As[k][m]
    __shared__ float Ws[8][128];   // Ws[k][n]

    const int rowBase = blockIdx.y * 128;
    const int colBase = blockIdx.x * 128;
    const int tid = threadIdx.x;

    const int arow = tid >> 1;
    const int ak4  = (tid & 1) * 4;
    const int wrow = tid >> 5;
    const int wc4  = (tid & 31) * 4;
    const int tm   = (tid >> 4) * 8;
    const int tn   = (tid & 15) * 8;

    float acc[8][8];
#pragma unroll
    for (int i = 0; i < 8; i++)
#pragma unroll
        for (int j = 0; j < 8; j++) acc[i][j] = 0.f;

    for (int k0 = 0; k0 < 512; k0 += 8) {
        float4 av = *(const float4*)&x[(size_t)(rowBase + arow) * 512 + k0 + ak4];
        As[ak4 + 0][arow] = av.x;
        As[ak4 + 1][arow] = av.y;
        As[ak4 + 2][arow] = av.z;
        As[ak4 + 3][arow] = av.w;
        *(float4*)&Ws[wrow][wc4] =
            *(const float4*)&W[(size_t)(k0 + wrow) * 2048 + colBase + wc4];
        __syncthreads();

#pragma unroll
        for (int kk = 0; kk < 8; kk++) {
            float a[8], w[8];
            *(float4*)&a[0] = *(const float4*)&As[kk][tm];
            *(float4*)&a[4] = *(const float4*)&As[kk][tm + 4];
            *(float4*)&w[0] = *(const float4*)&Ws[kk][tn];
            *(float4*)&w[4] = *(const float4*)&Ws[kk][tn + 4];
#pragma unroll
            for (int i = 0; i < 8; i++)
#pragma unroll
                for (int j = 0; j < 8; j++)
                    acc[i][j] = fmaf(a[i], w[j], acc[i][j]);
        }
        __syncthreads();
    }

    float bb[8];
    *(float4*)&bb[0] = *(const float4*)&bias[colBase + tn];
    *(float4*)&bb[4] = *(const float4*)&bias[colBase + tn + 4];

#pragma unroll
    for (int i = 0; i < 8; i++) {
        int r = rowBase + tm + i;
        int t = r & (T_ - 1);
        int b = r >> 11;
        float* dst = &g_xg[((size_t)t * B_ + b) * G_ + colBase + tn];
        float4 v0 = make_float4(acc[i][0] + bb[0], acc[i][1] + bb[1],
                                acc[i][2] + bb[2], acc[i][3] + bb[3]);
        float4 v1 = make_float4(acc[i][4] + bb[4], acc[i][5] + bb[5],
                                acc[i][6] + bb[6], acc[i][7] + bb[7]);
        *(float4*)&dst[0] = v0;
        *(float4*)&dst[4] = v1;
    }
}

// ---------------------------------------------------------------------------
// Kernel B: persistent recurrence — EXACT round-3 compute path and master
// barrier, with two isolated changes:
//  (1) out stores deferred past the arrive (release no longer drains scattered
//      DRAM stores; they overlap the barrier wait)
//  (2) polls use ld.volatile + one fence.acq_rel.gpu at exit
// ---------------------------------------------------------------------------
#define WSTRIDE 516
#define SM_WA   0
#define SM_WB   (8 * WSTRIDE)
#define SM_HS   (16 * WSTRIDE)
#define SM_GS   (SM_HS + 32 * WSTRIDE)
#define SM_CS   (SM_GS + 512)
#define SMEM_FLOATS (SM_CS + 128)

__global__ __launch_bounds__(256) void lstm_rec(const float* __restrict__ W,
                                                const float* __restrict__ h0,
                                                const float* __restrict__ c0,
                                                float* __restrict__ out) {
    extern __shared__ float sm[];
    float* Wa = sm + SM_WA;          // Wa[g2][k]
    float* Wb = sm + SM_WB;          // Wb[g2][k]
    float* hs = sm + SM_HS;          // hs[b][k], stride WSTRIDE
    float* gs = sm + SM_GS;          // gs[gl*32 + b]
    float* cs = sm + SM_CS;          // cs[hcl*32 + b]

    const int tid = threadIdx.x;
    const int j   = blockIdx.x;      // 0..127
    const int jb  = j * 4;

    // Load Wh slice into the two planes.
    for (int e = tid; e < 8192; e += 256) {
        int k  = e >> 4;
        int gl = e & 15;
        int gcol = (gl >> 2) * 512 + jb + (gl & 3);
        float v = W[(size_t)(512 + k) * 2048 + gcol];
        float* plane = (gl & 1) ? Wb : Wa;
        plane[(gl >> 1) * WSTRIDE + k] = v;
    }
    if (tid < 128) {
        int b = tid >> 2, hcl = tid & 3;
        cs[hcl * 32 + b] = c0[b * 512 + jb + hcl];
    }
    // Barrier bases (uniform at run start; monotone across graph replays).
    __shared__ unsigned s_fb, s_gb;
    if (tid == 0) {
        s_fb = *(volatile unsigned*)&g_flags[j];
        s_gb = *(volatile unsigned*)&g_go;
    }
    __syncthreads();
    const unsigned fbase = s_fb;
    const unsigned gbase = s_gb;

    const int b     = tid >> 3;            // 0..31
    const int g2    = tid & 7;             // 0..7
    const int gl0   = g2 * 2;
    const int gcol0 = (gl0 >> 2) * 512 + jb + (gl0 & 3);

    const float* wa = &Wa[g2 * WSTRIDE];
    const float* wb = &Wb[g2 * WSTRIDE];

    for (int t = 0; t < T_; t++) {
        // Prefetch xg for this thread (independent of h)
        float2 xg2 = *(const float2*)&g_xg[((size_t)t * B_ + b) * G_ + gcol0];

        // Broadcast current h into SMEM
        const float* hsrc = (t == 0) ? h0 : g_h[t & 1];
        for (int i4 = tid; i4 < 4096; i4 += 256) {
            int bb2 = i4 >> 7, k4 = (i4 & 127) * 4;
            *(float4*)&hs[bb2 * WSTRIDE + k4] = *(const float4*)&hsrc[bb2 * 512 + k4];
        }
        __syncthreads();

        // Two K=512 dot products per thread: 3x LDS.128 + 8 FFMA per 4 k.
        float acc0 = xg2.x, acc1 = xg2.y;
        const float* hrow = &hs[b * WSTRIDE];
#pragma unroll 4
        for (int k = 0; k < 512; k += 4) {
            float4 h4 = *(const float4*)&hrow[k];
            float4 a4 = *(const float4*)&wa[k];
            float4 b4 = *(const float4*)&wb[k];
            acc0 = fmaf(h4.x, a4.x, acc0); acc1 = fmaf(h4.x, b4.x, acc1);
            acc0 = fmaf(h4.y, a4.y, acc0); acc1 = fmaf(h4.y, b4.y, acc1);
            acc0 = fmaf(h4.z, a4.z, acc0); acc1 = fmaf(h4.z, b4.z, acc1);
            acc0 = fmaf(h4.w, a4.w, acc0); acc1 = fmaf(h4.w, b4.w, acc1);
        }
        gs[gl0 * 32 + b]       = acc0;
        gs[(gl0 + 1) * 32 + b] = acc1;
        __syncthreads();

        // Gate combine: 128 threads, one (b, hcl) each. Only the critical g_h
        // store happens before the arrive; out stores are deferred.
        float h_r = 0.f, c_r = 0.f;
        const int bb = tid >> 2, hcl = tid & 3;
        if (tid < 128) {
            float iv = gs[(0  + hcl) * 32 + bb];
            float fv = gs[(4  + hcl) * 32 + bb];
            float gv = gs[(8  + hcl) * 32 + bb];
            float ov = gs[(12 + hcl) * 32 + bb];
            iv = 1.f / (1.f + expf(-iv));
            fv = 1.f / (1.f + expf(-fv));
            gv = tanhf(gv);
            ov = 1.f / (1.f + expf(-ov));
            c_r = fv * cs[hcl * 32 + bb] + iv * gv;
            cs[hcl * 32 + bb] = c_r;
            h_r = ov * tanhf(c_r);
            g_h[(t + 1) & 1][bb * 512 + jb + hcl] = h_r;   // critical path only
        }
        __syncthreads();   // g_h stores done before the arrive below

        if (t < T_ - 1) {
            const unsigned step = (unsigned)t + 1u;
            if (tid == 0) st_rel_u32(&g_flags[j], fbase + step);  // arrive (tiny drain)

            // Deferred out store — overlaps the barrier wait below.
            if (tid < 128)
                out[((size_t)bb * T_ + t) * H_ + jb + hcl] = h_r;

            if (j == 0) {
                // Master: aggregate 128 flags (volatile poll), fence, release.
                if (tid < NCTA_REC) {
                    while ((int)(ld_vol_u32(&g_flags[tid]) - (fbase + step)) < 0) { }
                    fence_acq_rel_gpu();
                }
                __syncthreads();
                if (tid == 0) st_rel_u32(&g_go, gbase + step);
            } else {
                // Others: one thread polls the single release word.
                if (tid == 0) {
                    while ((int)(ld_vol_u32(&g_go) - (gbase + step)) < 0) { }
                    fence_acq_rel_gpu();
                }
                __syncthreads();
            }
        } else {
            // Last step: no barrier; store everything.
            if (tid < 128) {
                out[((size_t)bb * T_ + t) * H_ + jb + hcl]            = h_r;
                out[(size_t)BT_ * H_ + bb * 512 + jb + hcl]           = h_r;  // h_T
                out[(size_t)BT_ * H_ + B_ * H_ + bb * 512 + jb + hcl] = c_r;  // c_T
            }
        }
    }
}

// ---------------------------------------------------------------------------
// Launcher
// ---------------------------------------------------------------------------
extern "C" void kernel_launch(void* const* d_in, const int* in_sizes, int n_in,
                              void* d_out, int out_size) {
    const float* x    = (const float*)d_in[0];   // (B, T, D)
    const float* W    = (const float*)d_in[1];   // (D+H, 4H)
    const float* bias = (const float*)d_in[2];   // (4H,)
    const float* h0   = (const float*)d_in[3];   // (B, H)
    const float* c0   = (const float*)d_in[4];   // (B, H)
    float* out = (float*)d_out;                  // outputs | h_T | c_T

    dim3 grid(G_ / 128, BT_ / 128);
    xg_gemm<<<grid, 256>>>(x, W, bias);

    size_t smem = SMEM_FLOATS * sizeof(float);
    cudaFuncSetAttribute(lstm_rec, cudaFuncAttributeMaxDynamicSharedMemorySize,
                         (int)smem);
    lstm_rec<<<NCTA_REC, 256, smem>>>(W, h0, c0, out);
}

// round 8
// speedup vs baseline: 1.9874x; 1.4822x over previous
#include <cuda_runtime.h>
#include <math.h>

// Problem constants
#define B_  32
#define T_  2048
#define D_  512
#define H_  512
#define G_  2048          // 4*H
#define BT_ 65536         // B*T
#define NCTA_REC 128

// ---------------------------------------------------------------------------
// Scratch (device globals per harness rules: no cudaMalloc anywhere)
// ---------------------------------------------------------------------------
__device__ float g_xg[65536ULL * 2048ULL];   // (T, B, G) layout: xg[t][b][g]
__device__ float g_h[2][B_ * H_];            // double-buffered hidden state
__device__ unsigned g_flags[NCTA_REC];       // monotone per-CTA arrive flags
__device__ unsigned g_go;                    // monotone master release flag

__device__ __forceinline__ unsigned ld_acq_u32(const unsigned* p) {
    unsigned v;
    asm volatile("ld.acquire.gpu.global.u32 %0, [%1];" : "=r"(v) : "l"(p));
    return v;
}
__device__ __forceinline__ void st_rel_u32(unsigned* p, unsigned v) {
    asm volatile("st.release.gpu.global.u32 [%0], %1;" :: "l"(p), "r"(v));
}

// ---------------------------------------------------------------------------
// Kernel A: xg[t][b][g] = sum_d x[b][t][d] * W[d][g] + bias[g]
// fp32 SIMT GEMM, 128x128 tile, BK=8, 256 threads, 8x8 per-thread tile.
// (round-3 version, untouched)
// ---------------------------------------------------------------------------
__global__ __launch_bounds__(256) void xg_gemm(const float* __restrict__ x,
                                               const float* __restrict__ W,
                                               const float* __restrict__ bias) {
    __shared__ float As[8][128];   // As[k][m]
    __shared__ float Ws[8][128];   // Ws[k][n]

    const int rowBase = blockIdx.y * 128;
    const int colBase = blockIdx.x * 128;
    const int tid = threadIdx.x;

    const int arow = tid >> 1;
    const int ak4  = (tid & 1) * 4;
    const int wrow = tid >> 5;
    const int wc4  = (tid & 31) * 4;
    const int tm   = (tid >> 4) * 8;
    const int tn   = (tid & 15) * 8;

    float acc[8][8];
#pragma unroll
    for (int i = 0; i < 8; i++)
#pragma unroll
        for (int j = 0; j < 8; j++) acc[i][j] = 0.f;

    for (int k0 = 0; k0 < 512; k0 += 8) {
        float4 av = *(const float4*)&x[(size_t)(rowBase + arow) * 512 + k0 + ak4];
        As[ak4 + 0][arow] = av.x;
        As[ak4 + 1][arow] = av.y;
        As[ak4 + 2][arow] = av.z;
        As[ak4 + 3][arow] = av.w;
        *(float4*)&Ws[wrow][wc4] =
            *(const float4*)&W[(size_t)(k0 + wrow) * 2048 + colBase + wc4];
        __syncthreads();

#pragma unroll
        for (int kk = 0; kk < 8; kk++) {
            float a[8], w[8];
            *(float4*)&a[0] = *(const float4*)&As[kk][tm];
            *(float4*)&a[4] = *(const float4*)&As[kk][tm + 4];
            *(float4*)&w[0] = *(const float4*)&Ws[kk][tn];
            *(float4*)&w[4] = *(const float4*)&Ws[kk][tn + 4];
#pragma unroll
            for (int i = 0; i < 8; i++)
#pragma unroll
                for (int j = 0; j < 8; j++)
                    acc[i][j] = fmaf(a[i], w[j], acc[i][j]);
        }
        __syncthreads();
    }

    float bb[8];
    *(float4*)&bb[0] = *(const float4*)&bias[colBase + tn];
    *(float4*)&bb[4] = *(const float4*)&bias[colBase + tn + 4];

#pragma unroll
    for (int i = 0; i < 8; i++) {
        int r = rowBase + tm + i;
        int t = r & (T_ - 1);
        int b = r >> 11;
        float* dst = &g_xg[((size_t)t * B_ + b) * G_ + colBase + tn];
        float4 v0 = make_float4(acc[i][0] + bb[0], acc[i][1] + bb[1],
                                acc[i][2] + bb[2], acc[i][3] + bb[3]);
        float4 v1 = make_float4(acc[i][4] + bb[4], acc[i][5] + bb[5],
                                acc[i][6] + bb[6], acc[i][7] + bb[7]);
        *(float4*)&dst[0] = v0;
        *(float4*)&dst[4] = v1;
    }
}

// ---------------------------------------------------------------------------
// Kernel B: persistent recurrence. CTA j owns h-columns [4j, 4j+4) -> 16 gate
// columns (gl = gtype*4 + hcl). Barrier + store ordering = round-3 exact.
//
// NEW dot-phase mapping, bytes/FMA = 2, conflict-free by quarter-warp design:
//   warp  = bq (0..7): batches 4bq..4bq+3
//   quarter = gq (0..3): gate type gq, gate cols gl = 4gq..4gq+3
//   lane  = kq (0..7): K segment [64*kq, 64*kq+64)
//   per 4k: 8x LDS.128 (4 h rows + 4 W rows) for 64 FMA.
//   k-rotation ((i+kq)&15)*4 puts the 8 kq lanes of each quarter-warp in 8
//   distinct 16B bank groups -> zero LDS conflicts.
//   Partials: part[b][kq][gl], kq-stride 20 (STS.128 conflict-free),
//   b-stride 164 (combine scalar reads conflict-free); reduced + xg added in
//   the combine phase.
// ---------------------------------------------------------------------------
#define WSTRIDE  516
#define SM_W     0
#define SM_HS    (16 * WSTRIDE)               // 8256
#define SM_PART  (SM_HS + 32 * WSTRIDE)       // 24768
#define PART_BQ  20                           // kq stride (words)
#define PART_BB  164                          // b stride (words)
#define SM_CS    (SM_PART + 32 * PART_BB)     // 30016
#define SMEM_FLOATS (SM_CS + 128)             // 30144 floats = 120.6 KB

#define FMA4(ACC, H, Wv) \
    ACC = fmaf((H).x, (Wv).x, fmaf((H).y, (Wv).y, \
          fmaf((H).z, (Wv).z, fmaf((H).w, (Wv).w, ACC))))

__global__ __launch_bounds__(256) void lstm_rec(const float* __restrict__ W,
                                                const float* __restrict__ h0,
                                                const float* __restrict__ c0,
                                                float* __restrict__ out) {
    extern __shared__ float sm[];
    float* Ws16 = sm + SM_W;         // Ws16[gl*WSTRIDE + k], gl = gtype*4+hcl
    float* hs   = sm + SM_HS;        // hs[b*WSTRIDE + k]
    float* part = sm + SM_PART;      // part[b*164 + kq*20 + gl]
    float* cs   = sm + SM_CS;        // cs[hcl*32 + b]

    const int tid = threadIdx.x;
    const int j   = blockIdx.x;      // 0..127
    const int jb  = j * 4;

    // Load Wh slice: Ws16[gl][k]
    for (int e = tid; e < 8192; e += 256) {
        int k  = e >> 4;
        int gl = e & 15;
        int gcol = (gl >> 2) * 512 + jb + (gl & 3);
        Ws16[gl * WSTRIDE + k] = W[(size_t)(512 + k) * 2048 + gcol];
    }
    if (tid < 128) {
        int b = tid >> 2, hcl = tid & 3;
        cs[hcl * 32 + b] = c0[b * 512 + jb + hcl];
    }
    // Barrier bases (uniform at run start; monotone across graph replays).
    __shared__ unsigned s_fb, s_gb;
    if (tid == 0) {
        s_fb = *(volatile unsigned*)&g_flags[j];
        s_gb = *(volatile unsigned*)&g_go;
    }
    __syncthreads();
    const unsigned fbase = s_fb;
    const unsigned gbase = s_gb;

    // Dot-phase mapping
    const int bq = tid >> 5;         // warp: batch quad
    const int gq = (tid >> 3) & 3;   // quarter: gate type
    const int kq = tid & 7;          // lane-in-quarter: K segment
    const float* hb = &hs[(bq * 4) * WSTRIDE];
    const float* wb = &Ws16[(gq * 4) * WSTRIDE];
    const int kb = kq * 64;
    float* pst = &part[0 * PART_BB + kq * PART_BQ + gq * 4];  // + (4bq+ob)*PART_BB

    // Combine-phase mapping
    const int cb  = tid >> 2;        // 0..31 (valid when tid<128)
    const int hcl = tid & 3;

    for (int t = 0; t < T_; t++) {
        // xg for the combine phase (independent of h; in flight early)
        float gx0 = 0.f, gx1 = 0.f, gx2 = 0.f, gx3 = 0.f;
        if (tid < 128) {
            const float* xp = &g_xg[((size_t)t * B_ + cb) * G_ + jb + hcl];
            gx0 = xp[0];
            gx1 = xp[512];
            gx2 = xp[1024];
            gx3 = xp[1536];
        }

        // Broadcast current h into SMEM
        const float* hsrc = (t == 0) ? h0 : g_h[t & 1];
        for (int i4 = tid; i4 < 4096; i4 += 256) {
            int bb2 = i4 >> 7, k4 = (i4 & 127) * 4;
            *(float4*)&hs[bb2 * WSTRIDE + k4] = *(const float4*)&hsrc[bb2 * 512 + k4];
        }
        __syncthreads();

        // 4 batches x 4 gate cols x K=64 per thread: 8 LDS.128 + 64 FMA per 4k
        float a0x = 0.f, a0y = 0.f, a0z = 0.f, a0w = 0.f;
        float a1x = 0.f, a1y = 0.f, a1z = 0.f, a1w = 0.f;
        float a2x = 0.f, a2y = 0.f, a2z = 0.f, a2w = 0.f;
        float a3x = 0.f, a3y = 0.f, a3z = 0.f, a3w = 0.f;
#pragma unroll 4
        for (int i = 0; i < 16; i++) {
            int ko = kb + (((i + kq) & 15) << 2);
            float4 h0 = *(const float4*)&hb[0 * WSTRIDE + ko];
            float4 h1 = *(const float4*)&hb[1 * WSTRIDE + ko];
            float4 h2 = *(const float4*)&hb[2 * WSTRIDE + ko];
            float4 h3 = *(const float4*)&hb[3 * WSTRIDE + ko];
            float4 w0 = *(const float4*)&wb[0 * WSTRIDE + ko];
            float4 w1 = *(const float4*)&wb[1 * WSTRIDE + ko];
            float4 w2 = *(const float4*)&wb[2 * WSTRIDE + ko];
            float4 w3 = *(const float4*)&wb[3 * WSTRIDE + ko];
            FMA4(a0x, h0, w0); FMA4(a0y, h0, w1); FMA4(a0z, h0, w2); FMA4(a0w, h0, w3);
            FMA4(a1x, h1, w0); FMA4(a1y, h1, w1); FMA4(a1z, h1, w2); FMA4(a1w, h1, w3);
            FMA4(a2x, h2, w0); FMA4(a2y, h2, w1); FMA4(a2z, h2, w2); FMA4(a2w, h2, w3);
            FMA4(a3x, h3, w0); FMA4(a3y, h3, w1); FMA4(a3z, h3, w2); FMA4(a3w, h3, w3);
        }
        // Store 4x4 partials: 4x STS.128 (conflict-free via kq-stride 20)
        *(float4*)&pst[(4 * bq + 0) * PART_BB] = make_float4(a0x, a0y, a0z, a0w);
        *(float4*)&pst[(4 * bq + 1) * PART_BB] = make_float4(a1x, a1y, a1z, a1w);
        *(float4*)&pst[(4 * bq + 2) * PART_BB] = make_float4(a2x, a2y, a2z, a2w);
        *(float4*)&pst[(4 * bq + 3) * PART_BB] = make_float4(a3x, a3y, a3z, a3w);
        __syncthreads();

        // Gate combine: 128 threads, one (b, hcl) each; reduce 8 kq partials,
        // add xg, apply gates. Store ordering identical to round 3.
        if (tid < 128) {
            float s0 = gx0, s1 = gx1, s2 = gx2, s3 = gx3;
            const float* pb = &part[cb * PART_BB + hcl];
#pragma unroll
            for (int q = 0; q < 8; q++) {
                s0 += pb[q * PART_BQ + 0];
                s1 += pb[q * PART_BQ + 4];
                s2 += pb[q * PART_BQ + 8];
                s3 += pb[q * PART_BQ + 12];
            }
            float iv = 1.f / (1.f + expf(-s0));
            float fv = 1.f / (1.f + expf(-s1));
            float gv = tanhf(s2);
            float ov = 1.f / (1.f + expf(-s3));
            float c = fv * cs[hcl * 32 + cb] + iv * gv;
            cs[hcl * 32 + cb] = c;
            float h = ov * tanhf(c);
            g_h[(t + 1) & 1][cb * 512 + jb + hcl] = h;       // critical path
            out[((size_t)cb * T_ + t) * H_ + jb + hcl] = h;  // outputs[b][t][hc]
            if (t == T_ - 1) {
                out[(size_t)BT_ * H_ + cb * 512 + jb + hcl]           = h;  // h_T
                out[(size_t)BT_ * H_ + B_ * H_ + cb * 512 + jb + hcl] = c;  // c_T
            }
        }
        __syncthreads();   // all g_h stores done before the arrive below

        // Round-3 master-aggregated barrier (best measured variant).
        if (t < T_ - 1) {
            const unsigned step = (unsigned)t + 1u;
            if (tid == 0) st_rel_u32(&g_flags[j], fbase + step);  // arrive
            if (j == 0) {
                if (tid < NCTA_REC) {
                    while ((int)(ld_acq_u32(&g_flags[tid]) - (fbase + step)) < 0) { }
                }
                __syncthreads();
                if (tid == 0) st_rel_u32(&g_go, gbase + step);
            } else {
                if (tid == 0) {
                    while ((int)(ld_acq_u32(&g_go) - (gbase + step)) < 0) { }
                }
                __syncthreads();
            }
        }
    }
}

// ---------------------------------------------------------------------------
// Launcher
// ---------------------------------------------------------------------------
extern "C" void kernel_launch(void* const* d_in, const int* in_sizes, int n_in,
                              void* d_out, int out_size) {
    const float* x    = (const float*)d_in[0];   // (B, T, D)
    const float* W    = (const float*)d_in[1];   // (D+H, 4H)
    const float* bias = (const float*)d_in[2];   // (4H,)
    const float* h0   = (const float*)d_in[3];   // (B, H)
    const float* c0   = (const float*)d_in[4];   // (B, H)
    float* out = (float*)d_out;                  // outputs | h_T | c_T

    dim3 grid(G_ / 128, BT_ / 128);
    xg_gemm<<<grid, 256>>>(x, W, bias);

    size_t smem = SMEM_FLOATS * sizeof(float);
    cudaFuncSetAttribute(lstm_rec, cudaFuncAttributeMaxDynamicSharedMemorySize,
                         (int)smem);
    lstm_rec<<<NCTA_REC, 256, smem>>>(W, h0, c0, out);
}